// round 16
// baseline (speedup 1.0000x reference)
#include <cuda_runtime.h>
#include <cuda_bf16.h>
#include <cstdint>
#include <math.h>

#define T_STEPS 64
#define BATCH   64
#define HID     1024
#define VOC     32000
#define M2      128
#define TB      4096

typedef unsigned long long ull;
typedef __nv_bfloat16 bf16;

// ---------------- device scratch ----------------
__device__ float g_xpre[(size_t)TB * 3 * HID];
__device__ float g_ha[M2 * HID];                 // h ping (fp32 master)
__device__ float g_hb[M2 * HID];                 // h pong
__device__ float g_f[M2 * HID];                  // f gate
__device__ float g_brc[HID], g_bfc[HID], g_bhc[HID];
// per-phase split-K partial buffers (no aliasing across phases)
__device__ float g_p0[(size_t)8  * M2 * 2048];
__device__ float g_p1[(size_t)16 * M2 * 1024];
__device__ float g_p2[(size_t)8  * M2 * 2048];
__device__ float g_p3[(size_t)16 * M2 * 1024];
__device__ unsigned g_bar, g_bar2;
__device__ unsigned g_cnt[64];                   // GEMM->reduce group counters
__device__ unsigned g_r0d[128], g_r1d[128], g_r2d[128];  // reduce-done per CTA

// bf16 hi/lo split operands
__device__ __align__(16) bf16 g_haH[M2*HID], g_haL[M2*HID];
__device__ __align__(16) bf16 g_hbH[M2*HID], g_hbL[M2*HID];
__device__ __align__(16) bf16 g_rhH[M2*HID], g_rhL[M2*HID];
__device__ __align__(16) bf16 g_h1H[(size_t)TB * HID], g_h1L[(size_t)TB * HID];
__device__ __align__(16) bf16 g_xeH[(size_t)TB * HID], g_xeL[(size_t)TB * HID];
__device__ __align__(16) bf16 g_WdH[(size_t)VOC * HID], g_WdL[(size_t)VOC * HID];
__device__ __align__(16) bf16 g_Ur0H[HID*HID], g_Ur0L[HID*HID];
__device__ __align__(16) bf16 g_Uf0H[HID*HID], g_Uf0L[HID*HID];
__device__ __align__(16) bf16 g_Uh0H[HID*HID], g_Uh0L[HID*HID];
__device__ __align__(16) bf16 g_Wh1H[HID*HID], g_Wh1L[HID*HID];
__device__ __align__(16) bf16 g_Uh1H[HID*HID], g_Uh1L[HID*HID];
__device__ __align__(16) bf16 g_WUr1H[HID*HID], g_WUr1L[HID*HID];
__device__ __align__(16) bf16 g_WUf1H[HID*HID], g_WUf1L[HID*HID];
__device__ __align__(16) bf16 g_Wr0H[HID*HID], g_Wr0L[HID*HID];
__device__ __align__(16) bf16 g_Wf0H[HID*HID], g_Wf0L[HID*HID];
__device__ __align__(16) bf16 g_Wh0H[HID*HID], g_Wh0L[HID*HID];

__device__ __forceinline__ float sigm(float x) { return 1.0f / (1.0f + expf(-x)); }
__device__ __forceinline__ void wsplit(bf16* H, bf16* L, size_t idx, float v) {
    const bf16 h = __float2bfloat16(v);
    H[idx] = h;
    L[idx] = __float2bfloat16(v - __bfloat162float(h));
}

// -------- release/acquire primitives --------
__device__ __forceinline__ void atomAddRel(unsigned* p) {
    unsigned old;
    asm volatile("atom.add.release.gpu.u32 %0, [%1], 1;" : "=r"(old) : "l"(p) : "memory");
}
__device__ __forceinline__ unsigned ldAcq(unsigned* p) {
    unsigned v;
    asm volatile("ld.acquire.gpu.u32 %0, [%1];" : "=r"(v) : "l"(p) : "memory");
    return v;
}

// ================= mma.sync bf16x3 machinery =================
__device__ __forceinline__ uint32_t s2u(const void* p) {
    uint32_t a;
    asm("{ .reg .u64 t; cvta.to.shared.u64 t, %1; cvt.u32.u64 %0, t; }" : "=r"(a) : "l"(p));
    return a;
}
__device__ __forceinline__ void cpa16(uint32_t dst, const void* src) {
    asm volatile("cp.async.cg.shared.global [%0], [%1], 16;" :: "r"(dst), "l"(src) : "memory");
}
#define SW128(o) ((o) ^ (((o) >> 3) & 0x70))
#define STG 65536
#define REC_SMEM (2 * STG)
#define DEC_SMEM (3 * STG)

__device__ __forceinline__ void ldm4(uint32_t* r, uint32_t addr) {
    asm volatile("ldmatrix.sync.aligned.m8n8.x4.shared.b16 {%0,%1,%2,%3}, [%4];"
                 : "=r"(r[0]), "=r"(r[1]), "=r"(r[2]), "=r"(r[3]) : "r"(addr));
}
__device__ __forceinline__ void mma16816(float* d, const uint32_t* a, const uint32_t* b) {
    asm volatile(
        "mma.sync.aligned.m16n8k16.row.col.f32.bf16.bf16.f32 "
        "{%0,%1,%2,%3},{%4,%5,%6,%7},{%8,%9},{%0,%1,%2,%3};"
        : "+f"(d[0]), "+f"(d[1]), "+f"(d[2]), "+f"(d[3])
        : "r"(a[0]), "r"(a[1]), "r"(a[2]), "r"(a[3]), "r"(b[0]), "r"(b[1]));
}

__device__ __forceinline__ void ldchunk(uint32_t stg, const bf16* Ah, const bf16* Al,
                                        const bf16* Bh, const bf16* Bl)
{
    const int tid = threadIdx.x;
    const bf16* srcs[4] = { Ah, Al, Bh, Bl };
    #pragma unroll
    for (int arr = 0; arr < 4; arr++) {
        const uint32_t ab = stg + arr * 16384;
        #pragma unroll
        for (int i = 0; i < 4; i++) {
            const int g = tid + 256 * i;
            const int row = g >> 3, c = g & 7;
            cpa16(ab + SW128(row * 128 + c * 16), srcs[arr] + (size_t)row * HID + c * 8);
        }
    }
    asm volatile("cp.async.commit_group;" ::: "memory");
}

__device__ __forceinline__ void mma_stage(uint32_t stg, float (&acc)[4][4][4])
{
    const int lane = threadIdx.x & 31, wid = threadIdx.x >> 5;
    const int wm = wid >> 2, wn = wid & 3;
    const int rowa = wm * 64 + (lane & 7) + ((lane >> 3) & 1) * 8;
    const int cola_sel = (lane >> 4) * 16;
    const int rowb = wn * 32 + (lane & 7) + ((lane >> 4) & 1) * 8;
    const int colb_sel = ((lane >> 3) & 1) * 16;

    #pragma unroll
    for (int ks = 0; ks < 4; ks++) {
        uint32_t ah[4][4], al[4][4], bhp[2][4], blp[2][4];
        const int cola = ks * 32 + cola_sel;
        #pragma unroll
        for (int mt = 0; mt < 4; mt++) {
            const uint32_t ad = stg + SW128((rowa + mt * 16) * 128 + cola);
            ldm4(ah[mt], ad);
            ldm4(al[mt], ad + 16384);
        }
        const int colb = ks * 32 + colb_sel;
        #pragma unroll
        for (int p = 0; p < 2; p++) {
            const uint32_t bd = stg + 32768 + SW128((rowb + p * 16) * 128 + colb);
            ldm4(bhp[p], bd);
            ldm4(blp[p], bd + 16384);
        }
        #pragma unroll
        for (int mt = 0; mt < 4; mt++) {
            #pragma unroll
            for (int nt = 0; nt < 4; nt++) {
                const uint32_t* bh = &bhp[nt >> 1][(nt & 1) * 2];
                const uint32_t* bl = &blp[nt >> 1][(nt & 1) * 2];
                mma16816(acc[mt][nt], ah[mt], bh);
                mma16816(acc[mt][nt], ah[mt], bl);
                mma16816(acc[mt][nt], al[mt], bh);
            }
        }
    }
}

// Short-K (64 or 128) GEMM for the recurrence phases.
__device__ __forceinline__ void mma_gemm128(const bf16* Ah, const bf16* Al,
                                            const bf16* Bh, const bf16* Bl,
                                            int nchunks, float (&acc)[4][4][4], uint32_t sb)
{
    ldchunk(sb, Ah, Al, Bh, Bl);
    if (nchunks == 2) {
        ldchunk(sb + STG, Ah + 64, Al + 64, Bh + 64, Bl + 64);
        asm volatile("cp.async.wait_group 1;" ::: "memory");
        __syncthreads();
        mma_stage(sb, acc);
        asm volatile("cp.async.wait_group 0;" ::: "memory");
        __syncthreads();
        mma_stage(sb + STG, acc);
    } else {
        asm volatile("cp.async.wait_group 0;" ::: "memory");
        __syncthreads();
        mma_stage(sb, acc);
    }
    __syncthreads();
}

// Full K=1024 GEMM (pre/decoder): 3-stage cp.async ring.
__device__ __forceinline__ void mma_k1024(const bf16* Ah, const bf16* Al,
                                          const bf16* Bh, const bf16* Bl,
                                          float (&acc)[4][4][4], uint32_t sb)
{
    ldchunk(sb,        Ah,      Al,      Bh,      Bl);
    ldchunk(sb + STG,  Ah + 64, Al + 64, Bh + 64, Bl + 64);
    #pragma unroll 1
    for (int kc = 0; kc < 16; kc++) {
        if (kc < 15) asm volatile("cp.async.wait_group 1;" ::: "memory");
        else         asm volatile("cp.async.wait_group 0;" ::: "memory");
        __syncthreads();
        if (kc + 2 < 16) {
            const int o = (kc + 2) * 64;
            ldchunk(sb + ((kc + 2) % 3) * STG, Ah + o, Al + o, Bh + o, Bl + o);
        }
        mma_stage(sb + (kc % 3) * STG, acc);
    }
}

// ================= persistent recurrence kernel =================
#define REC_CTAS 128

__device__ __forceinline__ void gbar(unsigned nbar) {
    __syncthreads();
    if (threadIdx.x == 0) {
        atomAddRel(&g_bar);
        const unsigned tgt = (unsigned)REC_CTAS * nbar;
        while (ldAcq(&g_bar) < tgt) __nanosleep(8);
    }
    __syncthreads();
}

// GEMM->reduce group barrier (signal producer-group slot, wait reducer's group)
__device__ __forceinline__ void grpbar(int sig_slot, int wait_slot, unsigned tgt) {
    __syncthreads();
    if (threadIdx.x == 0) {
        atomAddRel(&g_cnt[sig_slot]);
        while (ldAcq(&g_cnt[wait_slot]) < tgt) __nanosleep(8);
    }
    __syncthreads();
}

// targeted wait on cnt producer-done counters arr[base..base+cnt)
__device__ __forceinline__ void waitN(unsigned* arr, int base, int cnt, unsigned tgt) {
    if ((int)threadIdx.x < cnt) {
        while (ldAcq(&arr[base + threadIdx.x]) < tgt) __nanosleep(8);
    }
    __syncthreads();
}
// publish this CTA's reduce-done (all threads' prior writes ordered via bar.sync)
__device__ __forceinline__ void sig1(unsigned* p) {
    __syncthreads();
    if (threadIdx.x == 0) atomAddRel(p);
}

__device__ __forceinline__ void stpart_mma(float* __restrict__ buf,
                                           float (&acc)[4][4][4], int ks, int ntile, int Ntot) {
    const int lane = threadIdx.x & 31, wid = threadIdx.x >> 5;
    const int wm = wid >> 2, wn = wid & 3;
    #pragma unroll
    for (int mt = 0; mt < 4; mt++) {
        const int r = wm * 64 + mt * 16 + (lane >> 2);
        #pragma unroll
        for (int nt = 0; nt < 4; nt++) {
            const int c = ntile * 128 + wn * 32 + nt * 8 + (lane & 3) * 2;
            float* base = buf + ((size_t)ks * M2 + r) * Ntot + c;
            *(float2*)base = make_float2(acc[mt][nt][0], acc[mt][nt][1]);
            *(float2*)(base + (size_t)8 * Ntot) = make_float2(acc[mt][nt][2], acc[mt][nt][3]);
        }
    }
}

__global__ __launch_bounds__(256)
void k_rec(const float* __restrict__ bur0, const float* __restrict__ buf0,
           const float* __restrict__ buh0)
{
    extern __shared__ __align__(128) char dsm[];
    const uint32_t sb = s2u(dsm);
    const int cta = blockIdx.x, tid = threadIdx.x;

    for (int t = 0; t < T_STEPS; t++) {
        const unsigned tg = (unsigned)(t + 1);
        // ========== p0 GEMM: [r|f]0 = ha @ [Ur0|Uf0].T (split-K 8, K=128) ==========
        {
            const int ntile = cta & 15, ks = cta >> 4, koff = ks * 128;
            const bf16* BH = (ntile < 8) ? g_Ur0H : g_Uf0H;
            const bf16* BL = (ntile < 8) ? g_Ur0L : g_Uf0L;
            const size_t wo = (size_t)((ntile & 7) * 128) * HID + koff;
            float acc[4][4][4] = {};
            mma_gemm128(g_haH + koff, g_haL + koff, BH + wo, BL + wo, 2, acc, sb);
            stpart_mma(g_p0, acc, ks, ntile, 2048);
        }
        grpbar(cta & 15, cta >> 3, 8 * tg);
        // ---- p0 reduce + sigmoid (slice n = cta*16) ----
        {
            const int m = tid >> 1, b = m & (BATCH - 1);
            const int n = cta * 16 + (tid & 1) * 8;
            float4 s0 = {0,0,0,0}, s1 = {0,0,0,0};
            #pragma unroll
            for (int ks = 0; ks < 8; ks++) {
                const float* p = g_p0 + ((size_t)ks * M2 + m) * 2048 + n;
                float4 v0 = __ldcg((const float4*)p), v1 = __ldcg((const float4*)(p + 4));
                s0.x += v0.x; s0.y += v0.y; s0.z += v0.z; s0.w += v0.w;
                s1.x += v1.x; s1.y += v1.y; s1.z += v1.z; s1.w += v1.w;
            }
            const int seg = n >> 10, nn = n & 1023;
            const float* bias = seg ? buf0 : bur0;
            float v[8] = {s0.x, s0.y, s0.z, s0.w, s1.x, s1.y, s1.z, s1.w};
            #pragma unroll
            for (int c = 0; c < 8; c++) {
                const float xadd = __ldg(g_xpre + ((size_t)t * BATCH + b) * (3 * HID) + n + c);
                const float g = sigm(v[c] + __ldg(bias + nn + c) + xadd);
                const int idx = m * HID + nn + c;
                if (seg == 0) {
                    const float rh = g * __ldcg(g_ha + idx);
                    wsplit(g_rhH, g_rhL, idx, rh);
                } else {
                    g_f[idx] = g;
                }
            }
        }
        sig1(&g_r0d[cta]);
        // ========== p1 GEMM: hw0 = rh @ Uh0.T (split-K 16, K=64) ==========
        {
            const int ntile = cta & 7, ks = cta >> 3, koff = ks * 64;
            waitN(g_r0d, 4 * ks, 4, tg);                 // rh k-slice producers
            const size_t wo = (size_t)(ntile * 128) * HID + koff;
            float acc[4][4][4] = {};
            mma_gemm128(g_rhH + koff, g_rhL + koff, g_Uh0H + wo, g_Uh0L + wo, 1, acc, sb);
            stpart_mma(g_p1, acc, ks, ntile, 1024);
        }
        grpbar(16 + (cta & 7), 16 + (cta >> 4), 16 * tg);
        // ---- p1 reduce + tanh + h update (slice n = cta*8) ----
        waitN(g_r0d, 64 + (cta >> 1), 1, tg);            // f producer
        {
            const int m = tid >> 1, b = m & (BATCH - 1);
            const int n = cta * 8 + (tid & 1) * 4;
            float4 s = {0,0,0,0};
            #pragma unroll
            for (int ks = 0; ks < 16; ks++) {
                float4 v = __ldcg((const float4*)(g_p1 + ((size_t)ks * M2 + m) * 1024 + n));
                s.x += v.x; s.y += v.y; s.z += v.z; s.w += v.w;
            }
            float v[4] = {s.x, s.y, s.z, s.w};
            #pragma unroll
            for (int c = 0; c < 4; c++) {
                const float xadd = __ldg(g_xpre + ((size_t)t * BATCH + b) * (3 * HID) + 2 * HID + n + c);
                const float hw = tanhf(v[c] + __ldg(buh0 + n + c) + xadd);
                const int idx = m * HID + n + c;
                const float h = __ldcg(g_ha + idx), f = __ldcg(g_f + idx);
                const float nh = h + f * (hw - h);
                g_hb[idx] = nh;
                wsplit(g_hbH, g_hbL, idx, nh);
            }
        }
        sig1(&g_r1d[cta]);
        // ========== p2 GEMM: [r|f]1 = hb @ [WUr1|WUf1].T (split-K 8, K=128) ==========
        {
            const int ntile = cta & 15, ks = cta >> 4, koff = ks * 128;
            waitN(g_r1d, 16 * ks, 16, tg);               // hb k-slice producers
            const bf16* BH = (ntile < 8) ? g_WUr1H : g_WUf1H;
            const bf16* BL = (ntile < 8) ? g_WUr1L : g_WUf1L;
            const size_t wo = (size_t)((ntile & 7) * 128) * HID + koff;
            float acc[4][4][4] = {};
            mma_gemm128(g_hbH + koff, g_hbL + koff, BH + wo, BL + wo, 2, acc, sb);
            stpart_mma(g_p2, acc, ks, ntile, 2048);
        }
        grpbar(32 + (cta & 15), 32 + (cta >> 3), 8 * tg);
        // ---- p2 reduce + sigmoid (hb read ordered transitively via grpbar chain) ----
        {
            const int m = tid >> 1;
            const int n = cta * 16 + (tid & 1) * 8;
            float4 s0 = {0,0,0,0}, s1 = {0,0,0,0};
            #pragma unroll
            for (int ks = 0; ks < 8; ks++) {
                const float* p = g_p2 + ((size_t)ks * M2 + m) * 2048 + n;
                float4 v0 = __ldcg((const float4*)p), v1 = __ldcg((const float4*)(p + 4));
                s0.x += v0.x; s0.y += v0.y; s0.z += v0.z; s0.w += v0.w;
                s1.x += v1.x; s1.y += v1.y; s1.z += v1.z; s1.w += v1.w;
            }
            const int seg = n >> 10, nn = n & 1023;
            float v[8] = {s0.x, s0.y, s0.z, s0.w, s1.x, s1.y, s1.z, s1.w};
            #pragma unroll
            for (int c = 0; c < 8; c++) {
                const int idx = m * HID + nn + c;
                if (seg == 0) {
                    const float r = sigm(v[c] + g_brc[nn + c]);
                    wsplit(g_rhH, g_rhL, idx, r * __ldcg(g_hb + idx));
                } else {
                    g_f[idx] = sigm(v[c] + g_bfc[nn + c]);
                }
            }
        }
        sig1(&g_r2d[cta]);
        // ========== p3 GEMM: hw1 = hb @ Wh1.T + rh @ Uh1.T (virtual K=2048, split 16) ==========
        {
            const int ntile = cta & 7, ks = cta >> 3;
            float acc[4][4][4] = {};
            if (ks < 8) {
                waitN(g_r1d, 16 * ks, 16, tg);           // hb producers
                const int koff = ks * 128;
                const size_t wo = (size_t)(ntile * 128) * HID + koff;
                mma_gemm128(g_hbH + koff, g_hbL + koff, g_Wh1H + wo, g_Wh1L + wo, 2, acc, sb);
            } else {
                waitN(g_r2d, 8 * (ks - 8), 8, tg);       // new rh producers
                const int koff = (ks - 8) * 128;
                const size_t wo = (size_t)(ntile * 128) * HID + koff;
                mma_gemm128(g_rhH + koff, g_rhL + koff, g_Uh1H + wo, g_Uh1L + wo, 2, acc, sb);
            }
            stpart_mma(g_p3, acc, ks, ntile, 1024);
        }
        grpbar(48 + (cta & 7), 48 + (cta >> 4), 16 * tg);
        // ---- p3 reduce + tanh + h update + h1 stash ----
        waitN(g_r2d, 64 + (cta >> 1), 1, tg);            // f producer
        {
            const int m = tid >> 1;
            const int n = cta * 8 + (tid & 1) * 4;
            float4 s = {0,0,0,0};
            #pragma unroll
            for (int ks = 0; ks < 16; ks++) {
                float4 v = __ldcg((const float4*)(g_p3 + ((size_t)ks * M2 + m) * 1024 + n));
                s.x += v.x; s.y += v.y; s.z += v.z; s.w += v.w;
            }
            float v[4] = {s.x, s.y, s.z, s.w};
            #pragma unroll
            for (int c = 0; c < 4; c++) {
                const float hw = tanhf(v[c] + g_bhc[n + c]);
                const int idx = m * HID + n + c;
                const float h = __ldcg(g_hb + idx), f = __ldcg(g_f + idx);
                const float nh = h + f * (hw - h);
                g_ha[idx] = nh;
                wsplit(g_haH, g_haL, idx, nh);
                if (m >= BATCH) {
                    const size_t o = ((size_t)t * BATCH + (m - BATCH)) * HID + n + c;
                    wsplit(g_h1H, g_h1L, o, nh);
                }
            }
        }
        // one global barrier per step: fences ALL cross-step RAW/WAR hazards
        if (t != T_STEPS - 1) gbar(tg);
    }

    // drain + reset all coordination state for the next graph replay
    __threadfence();
    __syncthreads();
    if (tid == 0) atomicAdd(&g_bar2, 1u);
    if (cta == 0) {
        if (tid == 0) {
            while (*(volatile unsigned*)&g_bar2 < (unsigned)REC_CTAS) __nanosleep(8);
        }
        __syncthreads();
        if (tid < 64) g_cnt[tid] = 0;
        if (tid < 128) { g_r0d[tid] = 0; g_r1d[tid] = 0; g_r2d[tid] = 0; }
        if (tid == 0) { g_bar = 0; g_bar2 = 0; }
        __threadfence();
    }
}

// ---------------- setup kernels ----------------
__global__ void k_hinit(const float* __restrict__ hidden) {
    int i = blockIdx.x * blockDim.x + threadIdx.x;
    if (i < M2 * HID) {
        const float v = hidden[i];
        g_ha[i] = v;
        wsplit(g_haH, g_haL, i, v);
    }
}
__global__ void k_hout(float* __restrict__ out) {
    int i = blockIdx.x * blockDim.x + threadIdx.x;
    if (i < M2 * HID) out[i] = g_ha[i];
}
__global__ void k_addb(const float* __restrict__ br1, const float* __restrict__ bur1,
                       const float* __restrict__ bf1, const float* __restrict__ buf1,
                       const float* __restrict__ bh1, const float* __restrict__ buh1) {
    int i = blockIdx.x * blockDim.x + threadIdx.x;
    if (i < HID) {
        g_brc[i] = br1[i] + bur1[i];
        g_bfc[i] = bf1[i] + buf1[i];
        g_bhc[i] = bh1[i] + buh1[i];
    }
}

__device__ __forceinline__ void split4(float4 v, bf16* H, bf16* L, size_t j) {
    const bf16 h0 = __float2bfloat16(v.x), h1 = __float2bfloat16(v.y);
    const bf16 h2 = __float2bfloat16(v.z), h3 = __float2bfloat16(v.w);
    ushort4 hv = { __bfloat16_as_ushort(h0), __bfloat16_as_ushort(h1),
                   __bfloat16_as_ushort(h2), __bfloat16_as_ushort(h3) };
    ((ushort4*)H)[j] = hv;
    ushort4 lv = { __bfloat16_as_ushort(__float2bfloat16(v.x - __bfloat162float(h0))),
                   __bfloat16_as_ushort(__float2bfloat16(v.y - __bfloat162float(h1))),
                   __bfloat16_as_ushort(__float2bfloat16(v.z - __bfloat162float(h2))),
                   __bfloat16_as_ushort(__float2bfloat16(v.w - __bfloat162float(h3))) };
    ((ushort4*)L)[j] = lv;
}

// One launch splits all 10 recurrence/pre weight matrices (grid.y selects).
__global__ void k_splitall(const float* __restrict__ Wr, const float* __restrict__ Wf,
                           const float* __restrict__ Wh, const float* __restrict__ Ur,
                           const float* __restrict__ Ufw, const float* __restrict__ Uh)
{
    const size_t HH = (size_t)HID * HID;
    const float *src, *src2 = nullptr;
    bf16 *H, *L;
    switch (blockIdx.y) {
        case 0: src = Ur;       H = g_Ur0H;  L = g_Ur0L;  break;
        case 1: src = Ufw;      H = g_Uf0H;  L = g_Uf0L;  break;
        case 2: src = Uh;       H = g_Uh0H;  L = g_Uh0L;  break;
        case 3: src = Wh + HH;  H = g_Wh1H;  L = g_Wh1L;  break;
        case 4: src = Uh + HH;  H = g_Uh1H;  L = g_Uh1L;  break;
        case 5: src = Wr;       H = g_Wr0H;  L = g_Wr0L;  break;
        case 6: src = Wf;       H = g_Wf0H;  L = g_Wf0L;  break;
        case 7: src = Wh;       H = g_Wh0H;  L = g_Wh0L;  break;
        case 8: src = Wr + HH;  src2 = Ur + HH;  H = g_WUr1H; L = g_WUr1L; break;
        default:src = Wf + HH;  src2 = Ufw + HH; H = g_WUf1H; L = g_WUf1L; break;
    }
    const size_t n4 = HH / 4;
    for (size_t j = (size_t)blockIdx.x * blockDim.x + threadIdx.x; j < n4;
         j += (size_t)gridDim.x * blockDim.x) {
        float4 v = __ldg((const float4*)src + j);
        if (src2) {
            float4 v2 = __ldg((const float4*)src2 + j);
            v.x += v2.x; v.y += v2.y; v.z += v2.z; v.w += v2.w;
        }
        split4(v, H, L, j);
    }
}

__global__ void k_splitW(const float* __restrict__ W) {
    const size_t n4 = (size_t)VOC * HID / 4;
    for (size_t j = (size_t)blockIdx.x * blockDim.x + threadIdx.x; j < n4;
         j += (size_t)gridDim.x * blockDim.x)
        split4(__ldg((const float4*)W + j), g_WdH, g_WdL, j);
}
__global__ void k_gather(const int* __restrict__ tokens, const float* __restrict__ emb) {
    const size_t n4 = (size_t)TB * HID / 4;
    for (size_t j = (size_t)blockIdx.x * blockDim.x + threadIdx.x; j < n4;
         j += (size_t)gridDim.x * blockDim.x) {
        const int row = (int)(j >> 8);
        const int c4  = (int)(j & 255);
        const int tok = __ldg(tokens + row);
        split4(__ldg((const float4*)(emb + (size_t)tok * HID) + c4), g_xeH, g_xeL, j);
    }
}

// ---------------- pre: xpre = xemb @ [Wr0|Wf0|Wh0].T + bias (bf16x3 mma) ----------------
__global__ __launch_bounds__(256)
void k_pre_mma(const float* __restrict__ b0, const float* __restrict__ b1,
               const float* __restrict__ b2)
{
    extern __shared__ __align__(128) char dsm[];
    const uint32_t sb = s2u(dsm);
    const int lane = threadIdx.x & 31, wid = threadIdx.x >> 5;
    const int wm = wid >> 2, wn = wid & 3;
    const int m0 = blockIdx.x * 128, n0g = blockIdx.y * 128;
    const int seg = n0g >> 10, nn0 = n0g & 1023;

    const bf16* BH = (seg == 0) ? g_Wr0H : (seg == 1) ? g_Wf0H : g_Wh0H;
    const bf16* BL = (seg == 0) ? g_Wr0L : (seg == 1) ? g_Wf0L : g_Wh0L;
    const float* bias = (seg == 0) ? b0 : (seg == 1) ? b1 : b2;

    float acc[4][4][4] = {};
    mma_k1024(g_xeH + (size_t)m0 * HID, g_xeL + (size_t)m0 * HID,
              BH + (size_t)nn0 * HID, BL + (size_t)nn0 * HID, acc, sb);

    #pragma unroll
    for (int mt = 0; mt < 4; mt++) {
        const int r = m0 + wm * 64 + mt * 16 + (lane >> 2);
        #pragma unroll
        for (int nt = 0; nt < 4; nt++) {
            const int cl = wn * 32 + nt * 8 + (lane & 3) * 2;
            const float2 bb = *(const float2*)(bias + nn0 + cl);
            float* d0 = g_xpre + (size_t)r * (3 * HID) + n0g + cl;
            *(float2*)d0 = make_float2(acc[mt][nt][0] + bb.x, acc[mt][nt][1] + bb.y);
            float* d1 = d0 + (size_t)8 * (3 * HID);
            *(float2*)d1 = make_float2(acc[mt][nt][2] + bb.x, acc[mt][nt][3] + bb.y);
        }
    }
}

// ---------------- decoder: logits = h1 @ Wdec.T + bdec (bf16x3 mma) ----------------
__global__ __launch_bounds__(256)
void k_dec_mma(const float* __restrict__ bdec, float* __restrict__ out)
{
    extern __shared__ __align__(128) char dsm[];
    const uint32_t sb = s2u(dsm);
    const int lane = threadIdx.x & 31, wid = threadIdx.x >> 5;
    const int wm = wid >> 2, wn = wid & 3;
    const int m0 = blockIdx.x * 128, n0 = blockIdx.y * 128;

    float acc[4][4][4] = {};
    mma_k1024(g_h1H + (size_t)m0 * HID, g_h1L + (size_t)m0 * HID,
              g_WdH + (size_t)n0 * HID, g_WdL + (size_t)n0 * HID, acc, sb);

    #pragma unroll
    for (int mt = 0; mt < 4; mt++) {
        const int r = m0 + wm * 64 + mt * 16 + (lane >> 2);
        #pragma unroll
        for (int nt = 0; nt < 4; nt++) {
            const int cc = n0 + wn * 32 + nt * 8 + (lane & 3) * 2;
            const float2 bb = *(const float2*)(bdec + cc);
            *(float2*)(out + (size_t)r * VOC + cc) =
                make_float2(acc[mt][nt][0] + bb.x, acc[mt][nt][1] + bb.y);
            *(float2*)(out + (size_t)(r + 8) * VOC + cc) =
                make_float2(acc[mt][nt][2] + bb.x, acc[mt][nt][3] + bb.y);
        }
    }
}

// ---------------- launch ----------------
extern "C" void kernel_launch(void* const* d_in, const int* in_sizes, int n_in,
                              void* d_out, int out_size)
{
    const int*   tokens = (const int*)  d_in[0];
    const float* hidden = (const float*)d_in[1];
    const float* emb    = (const float*)d_in[2];
    const float* Wr     = (const float*)d_in[3];
    const float* br     = (const float*)d_in[4];
    const float* Wf     = (const float*)d_in[5];
    const float* bf     = (const float*)d_in[6];
    const float* Wh     = (const float*)d_in[7];
    const float* bh     = (const float*)d_in[8];
    const float* Ur     = (const float*)d_in[9];
    const float* bur    = (const float*)d_in[10];
    const float* Ufw    = (const float*)d_in[11];
    const float* bufw   = (const float*)d_in[12];
    const float* Uh     = (const float*)d_in[13];
    const float* buh    = (const float*)d_in[14];
    const float* Wdec   = (const float*)d_in[15];
    const float* bdec   = (const float*)d_in[16];
    float* out = (float*)d_out;

    cudaFuncSetAttribute(k_rec,     cudaFuncAttributeMaxDynamicSharedMemorySize, REC_SMEM);
    cudaFuncSetAttribute(k_pre_mma, cudaFuncAttributeMaxDynamicSharedMemorySize, DEC_SMEM);
    cudaFuncSetAttribute(k_dec_mma, cudaFuncAttributeMaxDynamicSharedMemorySize, DEC_SMEM);

    k_hinit<<<(M2*HID + 1023) / 1024, 1024>>>(hidden);
    k_addb<<<4, 256>>>(br + HID, bur + HID, bf + HID, bufw + HID, bh + HID, buh + HID);

    k_splitall<<<dim3(128, 10), 256>>>(Wr, Wf, Wh, Ur, Ufw, Uh);
    k_splitW<<<2048, 256>>>(Wdec);
    k_gather<<<2048, 256>>>(tokens, emb);

    k_pre_mma<<<dim3(TB/128, 3*HID/128), 256, DEC_SMEM>>>(br, bf, bh);

    k_rec<<<REC_CTAS, 256, REC_SMEM>>>(bur, bufw, buh);

    k_dec_mma<<<dim3(TB/128, VOC/128), 256, DEC_SMEM>>>(bdec, out);

    const long long logits_elems = (long long)TB * VOC;
    if ((long long)out_size >= logits_elems + (long long)M2 * HID)
        k_hout<<<(M2*HID + 1023) / 1024, 1024>>>(out + logits_elems);
}